// round 12
// baseline (speedup 1.0000x reference)
#include <cuda_runtime.h>
#include <cuda_bf16.h>
#include <cstdint>

#define BB 8
#define SS 1024
#define EE 768
#define HH 12
#define PP 64

// ---------------------------------------------------------------------------
// Scratch (__device__ globals; allocation-free rule)
// ---------------------------------------------------------------------------
__device__ float g_K  [BB*SS*EE];   // tf32-rounded, [b][s][h][p]
__device__ float g_V  [BB*SS*EE];   // tf32-rounded
__device__ float g_QV [BB*SS*EE];   // tf32-rounded
__device__ float g_At [BB*SS*EE];   // tf32-rounded attn out, [m][hp]
__device__ float g_Xt [BB*SS*EE];   // tf32-rounded copy of x
__device__ float g_Qt [HH*SS*SS];   // tf32-rounded copy of q_heads
__device__ float g_WkT[EE*EE];      // Wk transposed: [(h,p)][e], tf32-rounded
__device__ float g_WvT[EE*EE];      // Wv transposed
__device__ float g_LtT[EE*EE];      // lifting transposed: [e_out][hp]

// ---------------------------------------------------------------------------
// helpers
// ---------------------------------------------------------------------------
__device__ __forceinline__ uint32_t f2tf32(float f) {
    uint32_t u;
    asm("cvt.rna.tf32.f32 %0, %1;" : "=r"(u) : "f"(f));
    return u;
}
__device__ __forceinline__ float rnd_tf32(float f) {
    return __uint_as_float(f2tf32(f));
}
__device__ __forceinline__ void mma_tf32(float c[4], const uint32_t a[4],
                                         const uint32_t b[2]) {
    asm volatile(
        "mma.sync.aligned.m16n8k8.row.col.f32.tf32.tf32.f32 "
        "{%0,%1,%2,%3}, {%4,%5,%6,%7}, {%8,%9}, {%0,%1,%2,%3};"
        : "+f"(c[0]), "+f"(c[1]), "+f"(c[2]), "+f"(c[3])
        : "r"(a[0]), "r"(a[1]), "r"(a[2]), "r"(a[3]), "r"(b[0]), "r"(b[1]));
}
__device__ __forceinline__ void cp_async16(void* sptr, const void* gptr) {
    uint32_t s = (uint32_t)__cvta_generic_to_shared(sptr);
    asm volatile("cp.async.cg.shared.global [%0], [%1], 16;\n"
                 :: "r"(s), "l"(gptr) : "memory");
}
#define CP_COMMIT() asm volatile("cp.async.commit_group;\n" ::: "memory")
#define CP_WAIT(n)  asm volatile("cp.async.wait_group %0;\n" :: "n"(n) : "memory")

__device__ __forceinline__ uint32_t smem_u32(const void* p) {
    return (uint32_t)__cvta_generic_to_shared(p);
}
__device__ __forceinline__ void ldsm_x4(uint32_t& r0, uint32_t& r1,
                                        uint32_t& r2, uint32_t& r3, uint32_t a) {
    asm volatile("ldmatrix.sync.aligned.m8n8.x4.shared.b16 {%0,%1,%2,%3}, [%4];"
                 : "=r"(r0), "=r"(r1), "=r"(r2), "=r"(r3) : "r"(a));
}

// ---------------------------------------------------------------------------
// Prepass: ONE sweep; rounds everything to tf32, transposes Wk/Wv/lifting.
// ---------------------------------------------------------------------------
#define N4_X  ((BB*SS*EE)/4)
#define N4_Q  ((HH*SS*SS)/4)
#define N4_W  ((HH*EE*PP)/4)
#define N4_L  ((EE*EE)/4)
#define N4_TOT (N4_X + N4_Q + 2*N4_W + N4_L)

__global__ void round_all_kernel(
    const float4* __restrict__ x,  const float4* __restrict__ q,
    const float4* __restrict__ wk, const float4* __restrict__ wv,
    const float4* __restrict__ lf,
    float4* __restrict__ ox,  float4* __restrict__ oq)
{
    int i = blockIdx.x * blockDim.x + threadIdx.x;
    if (i >= N4_TOT) return;
    if (i < N4_X + N4_Q) {
        const float4* src; float4* dst; int li;
        if (i < N4_X) { src = x; dst = ox; li = i; }
        else          { src = q; dst = oq; li = i - N4_X; }
        float4 v = src[li];
        v.x = rnd_tf32(v.x); v.y = rnd_tf32(v.y);
        v.z = rnd_tf32(v.z); v.w = rnd_tf32(v.w);
        dst[li] = v;
        return;
    }
    if (i < N4_X + N4_Q + 2*N4_W) {
        // W: [h][e][p] -> WT[(h*64+p)][e], rounded. float4 covers 4 p's.
        int li = i - (N4_X + N4_Q);
        const float4* src = wk; float* dst = g_WkT;
        if (li >= N4_W) { li -= N4_W; src = wv; dst = g_WvT; }
        float4 v = src[li];
        int idx = li * 4;
        int h = idx / (EE * PP);
        int rem = idx - h * (EE * PP);
        int e = rem / PP, p = rem - e * PP;
        float vals[4] = {v.x, v.y, v.z, v.w};
        #pragma unroll
        for (int j = 0; j < 4; j++)
            dst[(size_t)(h * PP + p + j) * EE + e] = rnd_tf32(vals[j]);
        return;
    }
    // lifting: [k=hp][n=e] -> LtT[n][k], rounded. float4 covers 4 n's.
    int li = i - (N4_X + N4_Q + 2*N4_W);
    float4 v = lf[li];
    int idx = li * 4;
    int k = idx / EE, n = idx - k * EE;
    float vals[4] = {v.x, v.y, v.z, v.w};
    #pragma unroll
    for (int j = 0; j < 4; j++)
        g_LtT[(size_t)(n + j) * EE + k] = rnd_tf32(vals[j]);
}

// ---------------------------------------------------------------------------
// GEMM geometry
// ---------------------------------------------------------------------------
#define BM 64
#define BN 128
#define BK 32
#define LDA 36
#define LDBK 36     // transposed-B row stride (k-length 32 + pad)
#define LDB 136     // k-major B row stride (qv only)
#define GEMM2_SMEM ((2*(BM*LDA + BN*LDBK)) * 4)   // full-LDSM kernels
#define GEMMQ_SMEM ((2*(BM*LDA + BK*LDB)) * 4)    // qv kernel

// ---------------------------------------------------------------------------
// Full-LDSM GEMM body (A [m][k] tile + B [n][k] tile, both LDSM).
// Template over output policy via caller-side epilogue; implemented twice
// (proj fused K/V, lift) to keep epilogues simple.
// ---------------------------------------------------------------------------

// ---- fused K/V projection: C[m][n=(h,p)] = X @ W^T-rows; z selects K/V.
// grid (EE/BN, 8192/BM, 2), 256 threads, 3 CTAs/SM.
__global__ __launch_bounds__(256, 3) void proj_tf32_kernel(
    const float* __restrict__ A,
    const float* __restrict__ BkT, const float* __restrict__ BvT,
    float* __restrict__ Ck, float* __restrict__ Cv)
{
    extern __shared__ float smx[];
    float* As = smx;
    float* Bs = smx + 2 * BM * LDA;

    const float* BT = blockIdx.z ? BvT : BkT;
    float* C = blockIdx.z ? Cv : Ck;

    const int tid = threadIdx.x;
    const int wid = tid >> 5, lane = tid & 31;
    const int gid = lane >> 2, tig = lane & 3;
    const int lr = lane & 7, sub = lane >> 3;
    const int warp_m = (wid >> 2) * 32;
    const int warp_n = (wid & 3) * 32;
    const int m0 = blockIdx.y * BM, n0 = blockIdx.x * BN;

    const uint32_t a_lane_off =
        (uint32_t)(((warp_m + lr + (sub & 1) * 8) * LDA + (sub >> 1) * 4) * 4);
    const uint32_t b_lane_off =
        (uint32_t)(((warp_n + lr + (sub >> 1) * 8) * LDBK + (sub & 1) * 4) * 4);
    const uint32_t As_u = smem_u32(As);
    const uint32_t Bs_u = smem_u32(Bs);

    float acc[2][4][4] = {};

    auto load_tile = [&](int k0, int stage) {
        float* Ad = As + stage * (BM * LDA);
        float* Bd = Bs + stage * (BN * LDBK);
        #pragma unroll
        for (int i = 0; i < 2; i++) {
            int f4 = tid + i * 256;
            int m = f4 >> 3, kc = (f4 & 7) * 4;
            cp_async16(&Ad[m * LDA + kc], &A[(size_t)(m0 + m) * EE + k0 + kc]);
        }
        #pragma unroll
        for (int i = 0; i < 4; i++) {
            int f4 = tid + i * 256;
            int r = f4 >> 3, kc = (f4 & 7) * 4;
            cp_async16(&Bd[r * LDBK + kc], &BT[(size_t)(n0 + r) * EE + k0 + kc]);
        }
    };

    const int ntiles = EE / BK;
    load_tile(0, 0); CP_COMMIT();

    for (int kt = 0; kt < ntiles; kt++) {
        if (kt + 1 < ntiles) {
            load_tile((kt + 1) * BK, (kt + 1) & 1);
            CP_COMMIT();
            CP_WAIT(1);
        } else {
            CP_WAIT(0);
        }
        __syncthreads();

        const uint32_t a_stage = As_u + (uint32_t)((kt & 1) * (BM * LDA) * 4) + a_lane_off;
        const uint32_t b_stage = Bs_u + (uint32_t)((kt & 1) * (BN * LDBK) * 4) + b_lane_off;
        #pragma unroll
        for (int ks = 0; ks < BK / 8; ks++) {
            const int kk = ks * 8;
            uint32_t af[2][4], bf[4][2];
            #pragma unroll
            for (int mt = 0; mt < 2; mt++)
                ldsm_x4(af[mt][0], af[mt][1], af[mt][2], af[mt][3],
                        a_stage + (uint32_t)((mt * 16 * LDA + kk) * 4));
            ldsm_x4(bf[0][0], bf[0][1], bf[1][0], bf[1][1],
                    b_stage + (uint32_t)(kk * 4));
            ldsm_x4(bf[2][0], bf[2][1], bf[3][0], bf[3][1],
                    b_stage + (uint32_t)((16 * LDBK + kk) * 4));
            #pragma unroll
            for (int mt = 0; mt < 2; mt++)
                #pragma unroll
                for (int nt = 0; nt < 4; nt++)
                    mma_tf32(acc[mt][nt], af[mt], bf[nt]);
        }
        __syncthreads();
    }

    #pragma unroll
    for (int mt = 0; mt < 2; mt++) {
        int r = m0 + warp_m + mt * 16 + gid;
        #pragma unroll
        for (int nt = 0; nt < 4; nt++) {
            int c = n0 + warp_n + nt * 8 + tig * 2;
            *(float2*)&C[(size_t)r * EE + c] =
                make_float2(rnd_tf32(acc[mt][nt][0]), rnd_tf32(acc[mt][nt][1]));
            *(float2*)&C[(size_t)(r + 8) * EE + c] =
                make_float2(rnd_tf32(acc[mt][nt][2]), rnd_tf32(acc[mt][nt][3]));
        }
    }
}

// ---- lift: out(8192x768) = g_At @ lifting (B from g_LtT [n][k]), fp32 out.
// grid (6, 128), 256 threads, 3 CTAs/SM.
__global__ __launch_bounds__(256, 3) void lift_tf32_kernel(float* __restrict__ C)
{
    extern __shared__ float smx[];
    float* As = smx;
    float* Bs = smx + 2 * BM * LDA;

    const int tid = threadIdx.x;
    const int wid = tid >> 5, lane = tid & 31;
    const int gid = lane >> 2, tig = lane & 3;
    const int lr = lane & 7, sub = lane >> 3;
    const int warp_m = (wid >> 2) * 32;
    const int warp_n = (wid & 3) * 32;
    const int m0 = blockIdx.y * BM, n0 = blockIdx.x * BN;

    const uint32_t a_lane_off =
        (uint32_t)(((warp_m + lr + (sub & 1) * 8) * LDA + (sub >> 1) * 4) * 4);
    const uint32_t b_lane_off =
        (uint32_t)(((warp_n + lr + (sub >> 1) * 8) * LDBK + (sub & 1) * 4) * 4);
    const uint32_t As_u = smem_u32(As);
    const uint32_t Bs_u = smem_u32(Bs);

    float acc[2][4][4] = {};

    auto load_tile = [&](int k0, int stage) {
        float* Ad = As + stage * (BM * LDA);
        float* Bd = Bs + stage * (BN * LDBK);
        #pragma unroll
        for (int i = 0; i < 2; i++) {
            int f4 = tid + i * 256;
            int m = f4 >> 3, kc = (f4 & 7) * 4;
            cp_async16(&Ad[m * LDA + kc], &g_At[(size_t)(m0 + m) * EE + k0 + kc]);
        }
        #pragma unroll
        for (int i = 0; i < 4; i++) {
            int f4 = tid + i * 256;
            int r = f4 >> 3, kc = (f4 & 7) * 4;
            cp_async16(&Bd[r * LDBK + kc], &g_LtT[(size_t)(n0 + r) * EE + k0 + kc]);
        }
    };

    const int ntiles = EE / BK;
    load_tile(0, 0); CP_COMMIT();

    for (int kt = 0; kt < ntiles; kt++) {
        if (kt + 1 < ntiles) {
            load_tile((kt + 1) * BK, (kt + 1) & 1);
            CP_COMMIT();
            CP_WAIT(1);
        } else {
            CP_WAIT(0);
        }
        __syncthreads();

        const uint32_t a_stage = As_u + (uint32_t)((kt & 1) * (BM * LDA) * 4) + a_lane_off;
        const uint32_t b_stage = Bs_u + (uint32_t)((kt & 1) * (BN * LDBK) * 4) + b_lane_off;
        #pragma unroll
        for (int ks = 0; ks < BK / 8; ks++) {
            const int kk = ks * 8;
            uint32_t af[2][4], bf[4][2];
            #pragma unroll
            for (int mt = 0; mt < 2; mt++)
                ldsm_x4(af[mt][0], af[mt][1], af[mt][2], af[mt][3],
                        a_stage + (uint32_t)((mt * 16 * LDA + kk) * 4));
            ldsm_x4(bf[0][0], bf[0][1], bf[1][0], bf[1][1],
                    b_stage + (uint32_t)(kk * 4));
            ldsm_x4(bf[2][0], bf[2][1], bf[3][0], bf[3][1],
                    b_stage + (uint32_t)((16 * LDBK + kk) * 4));
            #pragma unroll
            for (int mt = 0; mt < 2; mt++)
                #pragma unroll
                for (int nt = 0; nt < 4; nt++)
                    mma_tf32(acc[mt][nt], af[mt], bf[nt]);
        }
        __syncthreads();
    }

    #pragma unroll
    for (int mt = 0; mt < 2; mt++) {
        int r = m0 + warp_m + mt * 16 + gid;
        #pragma unroll
        for (int nt = 0; nt < 4; nt++) {
            int c = n0 + warp_n + nt * 8 + tig * 2;
            *(float2*)&C[(size_t)r * EE + c] =
                make_float2(acc[mt][nt][0], acc[mt][nt][1]);
            *(float2*)&C[(size_t)(r + 8) * EE + c] =
                make_float2(acc[mt][nt][2], acc[mt][nt][3]);
        }
    }
}

// ---------------------------------------------------------------------------
// QV GEMM per head (B scalar path, unchanged from R9/R10-passing):
//   QVcat(1024x512) = Q_h @ Vcat(1024x512)
//   Vcat[k][n] = g_V[((n>>6)*SS + k)*EE + h*PP + (n&63)]
// grid (4, 16, 12), 256 threads, 3 CTAs/SM.
// ---------------------------------------------------------------------------
__global__ __launch_bounds__(256, 3) void qv_tf32_kernel()
{
    extern __shared__ float smx[];
    float* As = smx;
    float* Bs = smx + 2 * BM * LDA;

    const int h = blockIdx.z;
    const int tid = threadIdx.x;
    const int wid = tid >> 5, lane = tid & 31;
    const int gid = lane >> 2, tig = lane & 3;
    const int lr = lane & 7, sub = lane >> 3;
    const int warp_m = (wid >> 2) * 32;
    const int warp_n = (wid & 3) * 32;
    const int m0 = blockIdx.y * BM, n0 = blockIdx.x * BN;

    const float* A  = g_Qt + (size_t)h * SS * SS;
    const float* Vb = g_V + h * PP;

    const uint32_t a_lane_off =
        (uint32_t)(((warp_m + lr + (sub & 1) * 8) * LDA + (sub >> 1) * 4) * 4);
    const uint32_t As_u = smem_u32(As);

    float acc[2][4][4] = {};

    auto load_tile = [&](int k0, int stage) {
        float* Ad = As + stage * (BM * LDA);
        float* Bd = Bs + stage * (BK * LDB);
        #pragma unroll
        for (int i = 0; i < 2; i++) {
            int f4 = tid + i * 256;
            int m = f4 >> 3, kc = (f4 & 7) * 4;
            cp_async16(&Ad[m * LDA + kc], &A[(size_t)(m0 + m) * SS + k0 + kc]);
        }
        #pragma unroll
        for (int i = 0; i < 4; i++) {
            int f4 = tid + i * 256;
            int k = f4 >> 5, nc = (f4 & 31) * 4;
            int n = n0 + nc;
            cp_async16(&Bd[k * LDB + nc],
                       &Vb[(size_t)((n >> 6) * SS + k0 + k) * EE + (n & 63)]);
        }
    };

    const int ntiles = SS / BK;
    load_tile(0, 0); CP_COMMIT();

    for (int kt = 0; kt < ntiles; kt++) {
        if (kt + 1 < ntiles) {
            load_tile((kt + 1) * BK, (kt + 1) & 1);
            CP_COMMIT();
            CP_WAIT(1);
        } else {
            CP_WAIT(0);
        }
        __syncthreads();

        const uint32_t a_stage = As_u + (uint32_t)((kt & 1) * (BM * LDA) * 4) + a_lane_off;
        const float* Bd = Bs + (kt & 1) * (BK * LDB);
        #pragma unroll
        for (int ks = 0; ks < BK / 8; ks++) {
            const int kk = ks * 8;
            uint32_t af[2][4], bf[4][2];
            #pragma unroll
            for (int mt = 0; mt < 2; mt++)
                ldsm_x4(af[mt][0], af[mt][1], af[mt][2], af[mt][3],
                        a_stage + (uint32_t)((mt * 16 * LDA + kk) * 4));
            #pragma unroll
            for (int nt = 0; nt < 4; nt++) {
                int n = warp_n + nt * 8 + gid;
                bf[nt][0] = __float_as_uint(Bd[(kk + tig) * LDB + n]);
                bf[nt][1] = __float_as_uint(Bd[(kk + tig + 4) * LDB + n]);
            }
            #pragma unroll
            for (int mt = 0; mt < 2; mt++)
                #pragma unroll
                for (int nt = 0; nt < 4; nt++)
                    mma_tf32(acc[mt][nt], af[mt], bf[nt]);
        }
        __syncthreads();
    }

    float* QVb = g_QV + h * PP;
    #pragma unroll
    for (int mt = 0; mt < 2; mt++) {
        int r = m0 + warp_m + mt * 16 + gid;
        #pragma unroll
        for (int nt = 0; nt < 4; nt++) {
            int n = n0 + warp_n + nt * 8 + tig * 2;
            int b_ = n >> 6, p = n & 63;
            *(float2*)&QVb[(size_t)(b_ * SS + r) * EE + p] =
                make_float2(rnd_tf32(acc[mt][nt][0]), rnd_tf32(acc[mt][nt][1]));
            *(float2*)&QVb[(size_t)(b_ * SS + r + 8) * EE + p] =
                make_float2(rnd_tf32(acc[mt][nt][2]), rnd_tf32(acc[mt][nt][3]));
        }
    }
}

// ---------------------------------------------------------------------------
// Tensor-core causal attention (race-fixed; LDSM). R9-verified version.
// ---------------------------------------------------------------------------
#define ALDK 68
#define ALDV 72
#define ATT_SMEM ((128*ALDK + 64*ALDK + 64*ALDV + 128*ALDK + 128*4) * 4)

__global__ __launch_bounds__(256, 2) void attn_mma_kernel()
{
    extern __shared__ float sm[];
    float* ks  = sm;                       // 128 x 68
    float* qs  = ks + 128 * ALDK;          // 64 x 68
    float* vs  = qs + 64 * ALDK;           // 64 x 72
    float* ps  = vs + 64 * ALDV;           // 128 x 68
    float* lsm = ps + 128 * ALDK;          // 128 x 4

    const int it = 7 - (int)blockIdx.x;    // heavy blocks first
    const int h = blockIdx.y, b = blockIdx.z;
    const int i0 = it * 128;
    const int tid = threadIdx.x;
    const int wid = tid >> 5, lane = tid & 31;
    const int gid = lane >> 2, tig = lane & 3;
    const int lr = lane & 7, sub = lane >> 3;
    const int wm = wid >> 2, wn = wid & 3;
    const int rbase = wm * 64;
    const int cbase = wn * 16;
    const float scale = 0.03608439182435161f;  // 1/sqrt(768)

    const uint32_t ksf = smem_u32(ks) +
        (uint32_t)(((rbase + lr + (sub & 1) * 8) * ALDK + (sub >> 1) * 4) * 4);
    const uint32_t qsf = smem_u32(qs) +
        (uint32_t)(((cbase + lr + (sub >> 1) * 8) * ALDK + (sub & 1) * 4) * 4);
    const uint32_t psf = smem_u32(ps) +
        (uint32_t)(((rbase + lr + (sub & 1) * 8) * ALDK + (sub >> 1) * 4) * 4);

    const float* Kb  = g_K  + (size_t)b * SS * EE + h * PP;
    const float* QVb = g_QV + (size_t)b * SS * EE + h * PP;
    const float* Vb  = g_V  + (size_t)b * SS * EE + h * PP;

    #pragma unroll
    for (int t = 0; t < 8; t++) {
        int idx = tid + t * 256;
        int r = idx >> 4, c4 = (idx & 15) * 4;
        cp_async16(&ks[r * ALDK + c4], &Kb[(size_t)(i0 + r) * EE + c4]);
    }
    CP_COMMIT();

    #pragma unroll
    for (int t = 0; t < 4; t++) {
        int idx = tid + t * 256;
        int r = idx >> 4, c4 = (idx & 15) * 4;
        cp_async16(&qs[r * ALDK + c4], &QVb[(size_t)r * EE + c4]);
    }
    CP_COMMIT();

    float Oa[4][2][4] = {};
    float lacc[4][2] = {};

    const int njt = 2 * it + 2;
    for (int jt = 0; jt < njt; jt++) {
        const int j0 = jt * 64;

        CP_WAIT(0);
        __syncthreads();

        #pragma unroll
        for (int t = 0; t < 4; t++) {
            int idx = tid + t * 256;
            int r = idx >> 4, c4 = (idx & 15) * 4;
            cp_async16(&vs[r * ALDV + c4], &Vb[(size_t)(j0 + r) * EE + c4]);
        }
        CP_COMMIT();

        float Sa[4][2][4] = {};
        #pragma unroll
        for (int kss = 0; kss < 8; kss++) {
            const int kk = kss * 8;
            uint32_t af[4][4], bf[2][2];
            #pragma unroll
            for (int mt = 0; mt < 4; mt++)
                ldsm_x4(af[mt][0], af[mt][1], af[mt][2], af[mt][3],
                        ksf + (uint32_t)((mt * 16 * ALDK + kk) * 4));
            ldsm_x4(bf[0][0], bf[0][1], bf[1][0], bf[1][1],
                    qsf + (uint32_t)(kk * 4));
            #pragma unroll
            for (int mt = 0; mt < 4; mt++)
                #pragma unroll
                for (int nt = 0; nt < 2; nt++)
                    mma_tf32(Sa[mt][nt], af[mt], bf[nt]);
        }

        const bool need_mask = (jt >= 2 * it);
        #pragma unroll
        for (int mt = 0; mt < 4; mt++) {
            #pragma unroll
            for (int nt = 0; nt < 2; nt++) {
                int rr0 = rbase + mt * 16 + gid;
                int cc = cbase + nt * 8 + 2 * tig;
                int iglob0 = i0 + rr0, iglob1 = iglob0 + 8;
                int jg = j0 + cc;
                float e0 = __expf(Sa[mt][nt][0] * scale);
                float e1 = __expf(Sa[mt][nt][1] * scale);
                float e2 = __expf(Sa[mt][nt][2] * scale);
                float e3 = __expf(Sa[mt][nt][3] * scale);
                if (need_mask) {
                    if (jg     > iglob0) e0 = 0.0f;
                    if (jg + 1 > iglob0) e1 = 0.0f;
                    if (jg     > iglob1) e2 = 0.0f;
                    if (jg + 1 > iglob1) e3 = 0.0f;
                }
                lacc[mt][0] += e0 + e1;
                lacc[mt][1] += e2 + e3;
                *(float2*)&ps[rr0 * ALDK + cc] =
                    make_float2(rnd_tf32(e0), rnd_tf32(e1));
                *(float2*)&ps[(rr0 + 8) * ALDK + cc] =
                    make_float2(rnd_tf32(e2), rnd_tf32(e3));
            }
        }
        CP_WAIT(0);
        __syncthreads();

        #pragma unroll
        for (int kss = 0; kss < 8; kss++) {
            const int kk = kss * 8;
            uint32_t af[4][4], bf[2][2];
            #pragma unroll
            for (int mt = 0; mt < 4; mt++)
                ldsm_x4(af[mt][0], af[mt][1], af[mt][2], af[mt][3],
                        psf + (uint32_t)((mt * 16 * ALDK + kk) * 4));
            #pragma unroll
            for (int nt = 0; nt < 2; nt++) {
                int n = cbase + nt * 8 + gid;
                bf[nt][0] = __float_as_uint(vs[(kk + tig) * ALDV + n]);
                bf[nt][1] = __float_as_uint(vs[(kk + tig + 4) * ALDV + n]);
            }
            #pragma unroll
            for (int mt = 0; mt < 4; mt++)
                #pragma unroll
                for (int nt = 0; nt < 2; nt++)
                    mma_tf32(Oa[mt][nt], af[mt], bf[nt]);
        }

        if (jt + 1 < njt) {
            const int jn = (jt + 1) * 64;
            #pragma unroll
            for (int t = 0; t < 4; t++) {
                int idx = tid + t * 256;
                int r = idx >> 4, c4 = (idx & 15) * 4;
                cp_async16(&qs[r * ALDK + c4], &QVb[(size_t)(jn + r) * EE + c4]);
            }
        }
        CP_COMMIT();
    }

    #pragma unroll
    for (int mt = 0; mt < 4; mt++) {
        #pragma unroll
        for (int rr = 0; rr < 2; rr++) {
            float v = lacc[mt][rr];
            v += __shfl_xor_sync(0xffffffffu, v, 1);
            v += __shfl_xor_sync(0xffffffffu, v, 2);
            lacc[mt][rr] = v;
        }
    }
    __syncthreads();
    if (tig == 0) {
        #pragma unroll
        for (int mt = 0; mt < 4; mt++) {
            int r = rbase + mt * 16 + gid;
            lsm[r * 4 + wn] = lacc[mt][0];
            lsm[(r + 8) * 4 + wn] = lacc[mt][1];
        }
    }
    __syncthreads();

    float* Ab = g_At + (size_t)b * SS * EE + h * PP;
    #pragma unroll
    for (int mt = 0; mt < 4; mt++) {
        int r = rbase + mt * 16 + gid;
        float inv0 = 1.0f / (lsm[r * 4] + lsm[r * 4 + 1] + lsm[r * 4 + 2] + lsm[r * 4 + 3]);
        int r8 = r + 8;
        float inv1 = 1.0f / (lsm[r8 * 4] + lsm[r8 * 4 + 1] + lsm[r8 * 4 + 2] + lsm[r8 * 4 + 3]);
        #pragma unroll
        for (int nt = 0; nt < 2; nt++) {
            int c = cbase + nt * 8 + 2 * tig;
            *(float2*)&Ab[(size_t)(i0 + r) * EE + c] =
                make_float2(rnd_tf32(Oa[mt][nt][0] * inv0), rnd_tf32(Oa[mt][nt][1] * inv0));
            *(float2*)&Ab[(size_t)(i0 + r8) * EE + c] =
                make_float2(rnd_tf32(Oa[mt][nt][2] * inv1), rnd_tf32(Oa[mt][nt][3] * inv1));
        }
    }
}

// ---------------------------------------------------------------------------
extern "C" void kernel_launch(void* const* d_in, const int* in_sizes, int n_in,
                              void* d_out, int out_size)
{
    const float* x    = (const float*)d_in[0];
    const float* wk   = (const float*)d_in[1];
    const float* wv   = (const float*)d_in[2];
    const float* q    = (const float*)d_in[3];
    const float* lift = (const float*)d_in[4];
    float* out = (float*)d_out;

    static bool attr_done = false;
    if (!attr_done) {
        cudaFuncSetAttribute(proj_tf32_kernel,
            cudaFuncAttributeMaxDynamicSharedMemorySize, GEMM2_SMEM);
        cudaFuncSetAttribute(lift_tf32_kernel,
            cudaFuncAttributeMaxDynamicSharedMemorySize, GEMM2_SMEM);
        cudaFuncSetAttribute(qv_tf32_kernel,
            cudaFuncAttributeMaxDynamicSharedMemorySize, GEMMQ_SMEM);
        cudaFuncSetAttribute(attn_mma_kernel,
            cudaFuncAttributeMaxDynamicSharedMemorySize, ATT_SMEM);
        attr_done = true;
    }

    float *gK, *gV, *gXt, *gQt, *gWkT, *gWvT;
    cudaGetSymbolAddress((void**)&gK,  g_K);
    cudaGetSymbolAddress((void**)&gV,  g_V);
    cudaGetSymbolAddress((void**)&gXt, g_Xt);
    cudaGetSymbolAddress((void**)&gQt, g_Qt);
    cudaGetSymbolAddress((void**)&gWkT, g_WkT);
    cudaGetSymbolAddress((void**)&gWvT, g_WvT);

    // --- prepass: round + transpose
    round_all_kernel<<<(N4_TOT + 255) / 256, 256>>>(
        (const float4*)x, (const float4*)q, (const float4*)wk,
        (const float4*)wv, (const float4*)lift,
        (float4*)gXt, (float4*)gQt);

    const int M = BB * SS;

    // --- fused K/V projections (full-LDSM)
    dim3 gp(EE / BN, M / BM, 2);
    proj_tf32_kernel<<<gp, 256, GEMM2_SMEM>>>(gXt, gWkT, gWvT, gK, gV);

    // --- QV = Q_h @ Vcat per head
    dim3 gq((BB * PP) / BN, SS / BM, HH);
    qv_tf32_kernel<<<gq, 256, GEMMQ_SMEM>>>();

    // --- causal attention
    dim3 ga(SS / 128, HH, BB);
    attn_mma_kernel<<<ga, 256, ATT_SMEM>>>();

    // --- out = attn @ lifting (full-LDSM, fp32 out)
    dim3 gl(EE / BN, M / BM);
    lift_tf32_kernel<<<gl, 256, GEMM2_SMEM>>>(out);
}

// round 13
// speedup vs baseline: 1.0354x; 1.0354x over previous
#include <cuda_runtime.h>
#include <cuda_bf16.h>
#include <cstdint>

#define BB 8
#define SS 1024
#define EE 768
#define HH 12
#define PP 64

// ---------------------------------------------------------------------------
// Scratch (__device__ globals; allocation-free rule)
// ---------------------------------------------------------------------------
__device__ float g_K  [BB*SS*EE];   // tf32-rounded, [b][s][h][p]
__device__ float g_V  [BB*SS*EE];   // tf32-rounded
__device__ float g_QV [BB*SS*EE];   // tf32-rounded
__device__ float g_At [BB*SS*EE];   // tf32-rounded attn out, [m][hp]
__device__ float g_WkT[EE*EE];      // Wk transposed: [(h,p)][e], tf32-rounded
__device__ float g_WvT[EE*EE];      // Wv transposed
__device__ float g_LtT[EE*EE];      // lifting transposed: [e_out][hp]

// ---------------------------------------------------------------------------
// helpers
// ---------------------------------------------------------------------------
__device__ __forceinline__ uint32_t f2tf32(float f) {
    uint32_t u;
    asm("cvt.rna.tf32.f32 %0, %1;" : "=r"(u) : "f"(f));
    return u;
}
__device__ __forceinline__ float rnd_tf32(float f) {
    return __uint_as_float(f2tf32(f));
}
__device__ __forceinline__ uint32_t rnd_bits(uint32_t u) {
    return f2tf32(__uint_as_float(u));
}
__device__ __forceinline__ void mma_tf32(float c[4], const uint32_t a[4],
                                         const uint32_t b[2]) {
    asm volatile(
        "mma.sync.aligned.m16n8k8.row.col.f32.tf32.tf32.f32 "
        "{%0,%1,%2,%3}, {%4,%5,%6,%7}, {%8,%9}, {%0,%1,%2,%3};"
        : "+f"(c[0]), "+f"(c[1]), "+f"(c[2]), "+f"(c[3])
        : "r"(a[0]), "r"(a[1]), "r"(a[2]), "r"(a[3]), "r"(b[0]), "r"(b[1]));
}
__device__ __forceinline__ void cp_async16(void* sptr, const void* gptr) {
    uint32_t s = (uint32_t)__cvta_generic_to_shared(sptr);
    asm volatile("cp.async.cg.shared.global [%0], [%1], 16;\n"
                 :: "r"(s), "l"(gptr) : "memory");
}
#define CP_COMMIT() asm volatile("cp.async.commit_group;\n" ::: "memory")
#define CP_WAIT(n)  asm volatile("cp.async.wait_group %0;\n" :: "n"(n) : "memory")

__device__ __forceinline__ uint32_t smem_u32(const void* p) {
    return (uint32_t)__cvta_generic_to_shared(p);
}
__device__ __forceinline__ void ldsm_x4(uint32_t& r0, uint32_t& r1,
                                        uint32_t& r2, uint32_t& r3, uint32_t a) {
    asm volatile("ldmatrix.sync.aligned.m8n8.x4.shared.b16 {%0,%1,%2,%3}, [%4];"
                 : "=r"(r0), "=r"(r1), "=r"(r2), "=r"(r3) : "r"(a));
}

// ---------------------------------------------------------------------------
// Prepass: rounds + transposes Wk/Wv (-> [(h,p)][e]) and lifting (-> [n][k]).
// x and q are no longer copied: their rounding happens in-register in the
// consuming GEMMs (identical rna on identical values -> bit-identical).
// ---------------------------------------------------------------------------
#define N4_W  ((HH*EE*PP)/4)
#define N4_L  ((EE*EE)/4)
#define N4_TOTW (2*N4_W + N4_L)

__global__ void round_w_kernel(
    const float4* __restrict__ wk, const float4* __restrict__ wv,
    const float4* __restrict__ lf)
{
    int i = blockIdx.x * blockDim.x + threadIdx.x;
    if (i >= N4_TOTW) return;
    if (i < 2*N4_W) {
        int li = i;
        const float4* src = wk; float* dst = g_WkT;
        if (li >= N4_W) { li -= N4_W; src = wv; dst = g_WvT; }
        float4 v = src[li];
        int idx = li * 4;
        int h = idx / (EE * PP);
        int rem = idx - h * (EE * PP);
        int e = rem / PP, p = rem - e * PP;
        float vals[4] = {v.x, v.y, v.z, v.w};
        #pragma unroll
        for (int j = 0; j < 4; j++)
            dst[(size_t)(h * PP + p + j) * EE + e] = rnd_tf32(vals[j]);
        return;
    }
    int li = i - 2*N4_W;
    float4 v = lf[li];
    int idx = li * 4;
    int k = idx / EE, n = idx - k * EE;
    float vals[4] = {v.x, v.y, v.z, v.w};
    #pragma unroll
    for (int j = 0; j < 4; j++)
        g_LtT[(size_t)(n + j) * EE + k] = rnd_tf32(vals[j]);
}

// ---------------------------------------------------------------------------
// GEMM geometry
// ---------------------------------------------------------------------------
#define BM 64
#define BN 128
#define BK 32
#define LDA 36
#define LDBK 36
#define LDB 136
#define GEMM2_SMEM ((2*(BM*LDA + BN*LDBK)) * 4)
#define GEMMQ_SMEM ((2*(BM*LDA + BK*LDB)) * 4)

// ---- fused K/V projection: A = raw x (rounded in-register after LDSM).
// grid (EE/BN, 8192/BM, 2), 256 threads, 3 CTAs/SM.
__global__ __launch_bounds__(256, 3) void proj_tf32_kernel(
    const float* __restrict__ A,
    const float* __restrict__ BkT, const float* __restrict__ BvT,
    float* __restrict__ Ck, float* __restrict__ Cv)
{
    extern __shared__ float smx[];
    float* As = smx;
    float* Bs = smx + 2 * BM * LDA;

    const float* BT = blockIdx.z ? BvT : BkT;
    float* C = blockIdx.z ? Cv : Ck;

    const int tid = threadIdx.x;
    const int wid = tid >> 5, lane = tid & 31;
    const int gid = lane >> 2, tig = lane & 3;
    const int lr = lane & 7, sub = lane >> 3;
    const int warp_m = (wid >> 2) * 32;
    const int warp_n = (wid & 3) * 32;
    const int m0 = blockIdx.y * BM, n0 = blockIdx.x * BN;

    const uint32_t a_lane_off =
        (uint32_t)(((warp_m + lr + (sub & 1) * 8) * LDA + (sub >> 1) * 4) * 4);
    const uint32_t b_lane_off =
        (uint32_t)(((warp_n + lr + (sub >> 1) * 8) * LDBK + (sub & 1) * 4) * 4);
    const uint32_t As_u = smem_u32(As);
    const uint32_t Bs_u = smem_u32(Bs);

    float acc[2][4][4] = {};

    auto load_tile = [&](int k0, int stage) {
        float* Ad = As + stage * (BM * LDA);
        float* Bd = Bs + stage * (BN * LDBK);
        #pragma unroll
        for (int i = 0; i < 2; i++) {
            int f4 = tid + i * 256;
            int m = f4 >> 3, kc = (f4 & 7) * 4;
            cp_async16(&Ad[m * LDA + kc], &A[(size_t)(m0 + m) * EE + k0 + kc]);
        }
        #pragma unroll
        for (int i = 0; i < 4; i++) {
            int f4 = tid + i * 256;
            int r = f4 >> 3, kc = (f4 & 7) * 4;
            cp_async16(&Bd[r * LDBK + kc], &BT[(size_t)(n0 + r) * EE + k0 + kc]);
        }
    };

    const int ntiles = EE / BK;
    load_tile(0, 0); CP_COMMIT();

    for (int kt = 0; kt < ntiles; kt++) {
        if (kt + 1 < ntiles) {
            load_tile((kt + 1) * BK, (kt + 1) & 1);
            CP_COMMIT();
            CP_WAIT(1);
        } else {
            CP_WAIT(0);
        }
        __syncthreads();

        const uint32_t a_stage = As_u + (uint32_t)((kt & 1) * (BM * LDA) * 4) + a_lane_off;
        const uint32_t b_stage = Bs_u + (uint32_t)((kt & 1) * (BN * LDBK) * 4) + b_lane_off;
        #pragma unroll
        for (int ks = 0; ks < BK / 8; ks++) {
            const int kk = ks * 8;
            uint32_t af[2][4], bf[4][2];
            #pragma unroll
            for (int mt = 0; mt < 2; mt++) {
                ldsm_x4(af[mt][0], af[mt][1], af[mt][2], af[mt][3],
                        a_stage + (uint32_t)((mt * 16 * LDA + kk) * 4));
                af[mt][0] = rnd_bits(af[mt][0]); af[mt][1] = rnd_bits(af[mt][1]);
                af[mt][2] = rnd_bits(af[mt][2]); af[mt][3] = rnd_bits(af[mt][3]);
            }
            ldsm_x4(bf[0][0], bf[0][1], bf[1][0], bf[1][1],
                    b_stage + (uint32_t)(kk * 4));
            ldsm_x4(bf[2][0], bf[2][1], bf[3][0], bf[3][1],
                    b_stage + (uint32_t)((16 * LDBK + kk) * 4));
            #pragma unroll
            for (int mt = 0; mt < 2; mt++)
                #pragma unroll
                for (int nt = 0; nt < 4; nt++)
                    mma_tf32(acc[mt][nt], af[mt], bf[nt]);
        }
        __syncthreads();
    }

    #pragma unroll
    for (int mt = 0; mt < 2; mt++) {
        int r = m0 + warp_m + mt * 16 + gid;
        #pragma unroll
        for (int nt = 0; nt < 4; nt++) {
            int c = n0 + warp_n + nt * 8 + tig * 2;
            *(float2*)&C[(size_t)r * EE + c] =
                make_float2(rnd_tf32(acc[mt][nt][0]), rnd_tf32(acc[mt][nt][1]));
            *(float2*)&C[(size_t)(r + 8) * EE + c] =
                make_float2(rnd_tf32(acc[mt][nt][2]), rnd_tf32(acc[mt][nt][3]));
        }
    }
}

// ---- lift: out(8192x768) = g_At @ lifting (B from g_LtT [n][k]), fp32 out.
__global__ __launch_bounds__(256, 3) void lift_tf32_kernel(float* __restrict__ C)
{
    extern __shared__ float smx[];
    float* As = smx;
    float* Bs = smx + 2 * BM * LDA;

    const int tid = threadIdx.x;
    const int wid = tid >> 5, lane = tid & 31;
    const int gid = lane >> 2, tig = lane & 3;
    const int lr = lane & 7, sub = lane >> 3;
    const int warp_m = (wid >> 2) * 32;
    const int warp_n = (wid & 3) * 32;
    const int m0 = blockIdx.y * BM, n0 = blockIdx.x * BN;

    const uint32_t a_lane_off =
        (uint32_t)(((warp_m + lr + (sub & 1) * 8) * LDA + (sub >> 1) * 4) * 4);
    const uint32_t b_lane_off =
        (uint32_t)(((warp_n + lr + (sub >> 1) * 8) * LDBK + (sub & 1) * 4) * 4);
    const uint32_t As_u = smem_u32(As);
    const uint32_t Bs_u = smem_u32(Bs);

    float acc[2][4][4] = {};

    auto load_tile = [&](int k0, int stage) {
        float* Ad = As + stage * (BM * LDA);
        float* Bd = Bs + stage * (BN * LDBK);
        #pragma unroll
        for (int i = 0; i < 2; i++) {
            int f4 = tid + i * 256;
            int m = f4 >> 3, kc = (f4 & 7) * 4;
            cp_async16(&Ad[m * LDA + kc], &g_At[(size_t)(m0 + m) * EE + k0 + kc]);
        }
        #pragma unroll
        for (int i = 0; i < 4; i++) {
            int f4 = tid + i * 256;
            int r = f4 >> 3, kc = (f4 & 7) * 4;
            cp_async16(&Bd[r * LDBK + kc], &g_LtT[(size_t)(n0 + r) * EE + k0 + kc]);
        }
    };

    const int ntiles = EE / BK;
    load_tile(0, 0); CP_COMMIT();

    for (int kt = 0; kt < ntiles; kt++) {
        if (kt + 1 < ntiles) {
            load_tile((kt + 1) * BK, (kt + 1) & 1);
            CP_COMMIT();
            CP_WAIT(1);
        } else {
            CP_WAIT(0);
        }
        __syncthreads();

        const uint32_t a_stage = As_u + (uint32_t)((kt & 1) * (BM * LDA) * 4) + a_lane_off;
        const uint32_t b_stage = Bs_u + (uint32_t)((kt & 1) * (BN * LDBK) * 4) + b_lane_off;
        #pragma unroll
        for (int ks = 0; ks < BK / 8; ks++) {
            const int kk = ks * 8;
            uint32_t af[2][4], bf[4][2];
            #pragma unroll
            for (int mt = 0; mt < 2; mt++)
                ldsm_x4(af[mt][0], af[mt][1], af[mt][2], af[mt][3],
                        a_stage + (uint32_t)((mt * 16 * LDA + kk) * 4));
            ldsm_x4(bf[0][0], bf[0][1], bf[1][0], bf[1][1],
                    b_stage + (uint32_t)(kk * 4));
            ldsm_x4(bf[2][0], bf[2][1], bf[3][0], bf[3][1],
                    b_stage + (uint32_t)((16 * LDBK + kk) * 4));
            #pragma unroll
            for (int mt = 0; mt < 2; mt++)
                #pragma unroll
                for (int nt = 0; nt < 4; nt++)
                    mma_tf32(acc[mt][nt], af[mt], bf[nt]);
        }
        __syncthreads();
    }

    #pragma unroll
    for (int mt = 0; mt < 2; mt++) {
        int r = m0 + warp_m + mt * 16 + gid;
        #pragma unroll
        for (int nt = 0; nt < 4; nt++) {
            int c = n0 + warp_n + nt * 8 + tig * 2;
            *(float2*)&C[(size_t)r * EE + c] =
                make_float2(acc[mt][nt][0], acc[mt][nt][1]);
            *(float2*)&C[(size_t)(r + 8) * EE + c] =
                make_float2(acc[mt][nt][2], acc[mt][nt][3]);
        }
    }
}

// ---------------------------------------------------------------------------
// QV GEMM per head: A = raw q (rounded in-register after LDSM).
//   QVcat(1024x512) = Q_h @ Vcat;  Vcat[k][n] = g_V[((n>>6)*SS+k)*EE+h*PP+(n&63)]
// grid (4, 16, 12), 256 threads, 3 CTAs/SM.
// ---------------------------------------------------------------------------
__global__ __launch_bounds__(256, 3) void qv_tf32_kernel(const float* __restrict__ q)
{
    extern __shared__ float smx[];
    float* As = smx;
    float* Bs = smx + 2 * BM * LDA;

    const int h = blockIdx.z;
    const int tid = threadIdx.x;
    const int wid = tid >> 5, lane = tid & 31;
    const int gid = lane >> 2, tig = lane & 3;
    const int lr = lane & 7, sub = lane >> 3;
    const int warp_m = (wid >> 2) * 32;
    const int warp_n = (wid & 3) * 32;
    const int m0 = blockIdx.y * BM, n0 = blockIdx.x * BN;

    const float* A  = q + (size_t)h * SS * SS;
    const float* Vb = g_V + h * PP;

    const uint32_t a_lane_off =
        (uint32_t)(((warp_m + lr + (sub & 1) * 8) * LDA + (sub >> 1) * 4) * 4);
    const uint32_t As_u = smem_u32(As);

    float acc[2][4][4] = {};

    auto load_tile = [&](int k0, int stage) {
        float* Ad = As + stage * (BM * LDA);
        float* Bd = Bs + stage * (BK * LDB);
        #pragma unroll
        for (int i = 0; i < 2; i++) {
            int f4 = tid + i * 256;
            int m = f4 >> 3, kc = (f4 & 7) * 4;
            cp_async16(&Ad[m * LDA + kc], &A[(size_t)(m0 + m) * SS + k0 + kc]);
        }
        #pragma unroll
        for (int i = 0; i < 4; i++) {
            int f4 = tid + i * 256;
            int k = f4 >> 5, nc = (f4 & 31) * 4;
            int n = n0 + nc;
            cp_async16(&Bd[k * LDB + nc],
                       &Vb[(size_t)((n >> 6) * SS + k0 + k) * EE + (n & 63)]);
        }
    };

    const int ntiles = SS / BK;
    load_tile(0, 0); CP_COMMIT();

    for (int kt = 0; kt < ntiles; kt++) {
        if (kt + 1 < ntiles) {
            load_tile((kt + 1) * BK, (kt + 1) & 1);
            CP_COMMIT();
            CP_WAIT(1);
        } else {
            CP_WAIT(0);
        }
        __syncthreads();

        const uint32_t a_stage = As_u + (uint32_t)((kt & 1) * (BM * LDA) * 4) + a_lane_off;
        const float* Bd = Bs + (kt & 1) * (BK * LDB);
        #pragma unroll
        for (int ks = 0; ks < BK / 8; ks++) {
            const int kk = ks * 8;
            uint32_t af[2][4], bf[4][2];
            #pragma unroll
            for (int mt = 0; mt < 2; mt++) {
                ldsm_x4(af[mt][0], af[mt][1], af[mt][2], af[mt][3],
                        a_stage + (uint32_t)((mt * 16 * LDA + kk) * 4));
                af[mt][0] = rnd_bits(af[mt][0]); af[mt][1] = rnd_bits(af[mt][1]);
                af[mt][2] = rnd_bits(af[mt][2]); af[mt][3] = rnd_bits(af[mt][3]);
            }
            #pragma unroll
            for (int nt = 0; nt < 4; nt++) {
                int n = warp_n + nt * 8 + gid;
                bf[nt][0] = __float_as_uint(Bd[(kk + tig) * LDB + n]);
                bf[nt][1] = __float_as_uint(Bd[(kk + tig + 4) * LDB + n]);
            }
            #pragma unroll
            for (int mt = 0; mt < 2; mt++)
                #pragma unroll
                for (int nt = 0; nt < 4; nt++)
                    mma_tf32(acc[mt][nt], af[mt], bf[nt]);
        }
        __syncthreads();
    }

    float* QVb = g_QV + h * PP;
    #pragma unroll
    for (int mt = 0; mt < 2; mt++) {
        int r = m0 + warp_m + mt * 16 + gid;
        #pragma unroll
        for (int nt = 0; nt < 4; nt++) {
            int n = n0 + warp_n + nt * 8 + tig * 2;
            int b_ = n >> 6, p = n & 63;
            *(float2*)&QVb[(size_t)(b_ * SS + r) * EE + p] =
                make_float2(rnd_tf32(acc[mt][nt][0]), rnd_tf32(acc[mt][nt][1]));
            *(float2*)&QVb[(size_t)(b_ * SS + r + 8) * EE + p] =
                make_float2(rnd_tf32(acc[mt][nt][2]), rnd_tf32(acc[mt][nt][3]));
        }
    }
}

// ---------------------------------------------------------------------------
// Tensor-core causal attention, 64-row i-blocks, 3 CTAs/SM.
// Same math/accumulation order per output row as the 128-row version
// (masked tiles contributed exact zeros) -> bit-identical results.
// grid (16, 12, 8); njt = it+1; mask only on the diagonal tile.
// ---------------------------------------------------------------------------
#define ALDK 68
#define ALDV 72
#define ATT_SMEM ((64*ALDK + 64*ALDK + 64*ALDV + 64*ALDK + 64*4) * 4)

__global__ __launch_bounds__(256, 3) void attn_mma_kernel()
{
    extern __shared__ float sm[];
    float* ks  = sm;                      // 64 x 68
    float* qs  = ks + 64 * ALDK;          // 64 x 68
    float* vs  = qs + 64 * ALDK;          // 64 x 72
    float* ps  = vs + 64 * ALDV;          // 64 x 68
    float* lsm = ps + 64 * ALDK;          // 64 x 4

    const int it = 15 - (int)blockIdx.x;  // heavy blocks first
    const int h = blockIdx.y, b = blockIdx.z;
    const int i0 = it * 64;
    const int tid = threadIdx.x;
    const int wid = tid >> 5, lane = tid & 31;
    const int gid = lane >> 2, tig = lane & 3;
    const int lr = lane & 7, sub = lane >> 3;
    const int wm = wid >> 2, wn = wid & 3;
    const int rbase = wm * 32;
    const int cbase = wn * 16;
    const float scale = 0.03608439182435161f;  // 1/sqrt(768)

    const uint32_t ksf = smem_u32(ks) +
        (uint32_t)(((rbase + lr + (sub & 1) * 8) * ALDK + (sub >> 1) * 4) * 4);
    const uint32_t qsf = smem_u32(qs) +
        (uint32_t)(((cbase + lr + (sub >> 1) * 8) * ALDK + (sub & 1) * 4) * 4);
    const uint32_t psf = smem_u32(ps) +
        (uint32_t)(((rbase + lr + (sub & 1) * 8) * ALDK + (sub >> 1) * 4) * 4);

    const float* Kb  = g_K  + (size_t)b * SS * EE + h * PP;
    const float* QVb = g_QV + (size_t)b * SS * EE + h * PP;
    const float* Vb  = g_V  + (size_t)b * SS * EE + h * PP;

    // persistent K tile (64 x 64)
    #pragma unroll
    for (int t = 0; t < 4; t++) {
        int idx = tid + t * 256;
        int r = idx >> 4, c4 = (idx & 15) * 4;
        cp_async16(&ks[r * ALDK + c4], &Kb[(size_t)(i0 + r) * EE + c4]);
    }
    CP_COMMIT();

    // prefetch qs(0)
    #pragma unroll
    for (int t = 0; t < 4; t++) {
        int idx = tid + t * 256;
        int r = idx >> 4, c4 = (idx & 15) * 4;
        cp_async16(&qs[r * ALDK + c4], &QVb[(size_t)r * EE + c4]);
    }
    CP_COMMIT();

    float Oa[2][2][4] = {};
    float lacc[2][2] = {};

    const int njt = it + 1;
    for (int jt = 0; jt < njt; jt++) {
        const int j0 = jt * 64;

        CP_WAIT(0);          // qs(jt) (and ks on jt=0) arrived
        __syncthreads();     // all warps done with PV(jt-1) -> vs/ps writable

        #pragma unroll
        for (int t = 0; t < 4; t++) {
            int idx = tid + t * 256;
            int r = idx >> 4, c4 = (idx & 15) * 4;
            cp_async16(&vs[r * ALDV + c4], &Vb[(size_t)(j0 + r) * EE + c4]);
        }
        CP_COMMIT();

        // ---- S = K @ QV^T  (M=64 i, N=64 j, K=64 p)
        float Sa[2][2][4] = {};
        #pragma unroll
        for (int kss = 0; kss < 8; kss++) {
            const int kk = kss * 8;
            uint32_t af[2][4], bf[2][2];
            #pragma unroll
            for (int mt = 0; mt < 2; mt++)
                ldsm_x4(af[mt][0], af[mt][1], af[mt][2], af[mt][3],
                        ksf + (uint32_t)((mt * 16 * ALDK + kk) * 4));
            ldsm_x4(bf[0][0], bf[0][1], bf[1][0], bf[1][1],
                    qsf + (uint32_t)(kk * 4));
            #pragma unroll
            for (int mt = 0; mt < 2; mt++)
                #pragma unroll
                for (int nt = 0; nt < 2; nt++)
                    mma_tf32(Sa[mt][nt], af[mt], bf[nt]);
        }

        // ---- mask + exp, write P tile (tf32), accumulate row sums
        const bool need_mask = (jt == it);
        #pragma unroll
        for (int mt = 0; mt < 2; mt++) {
            #pragma unroll
            for (int nt = 0; nt < 2; nt++) {
                int rr0 = rbase + mt * 16 + gid;
                int cc = cbase + nt * 8 + 2 * tig;
                int iglob0 = i0 + rr0, iglob1 = iglob0 + 8;
                int jg = j0 + cc;
                float e0 = __expf(Sa[mt][nt][0] * scale);
                float e1 = __expf(Sa[mt][nt][1] * scale);
                float e2 = __expf(Sa[mt][nt][2] * scale);
                float e3 = __expf(Sa[mt][nt][3] * scale);
                if (need_mask) {
                    if (jg     > iglob0) e0 = 0.0f;
                    if (jg + 1 > iglob0) e1 = 0.0f;
                    if (jg     > iglob1) e2 = 0.0f;
                    if (jg + 1 > iglob1) e3 = 0.0f;
                }
                lacc[mt][0] += e0 + e1;
                lacc[mt][1] += e2 + e3;
                *(float2*)&ps[rr0 * ALDK + cc] =
                    make_float2(rnd_tf32(e0), rnd_tf32(e1));
                *(float2*)&ps[(rr0 + 8) * ALDK + cc] =
                    make_float2(rnd_tf32(e2), rnd_tf32(e3));
            }
        }
        CP_WAIT(0);          // vs(jt) arrived (hidden behind S-mma + exp)
        __syncthreads();     // P tile complete, vs visible

        // ---- O += P @ V  (M=64 i, N=64 p, K=64 j)
        #pragma unroll
        for (int kss = 0; kss < 8; kss++) {
            const int kk = kss * 8;
            uint32_t af[2][4], bf[2][2];
            #pragma unroll
            for (int mt = 0; mt < 2; mt++)
                ldsm_x4(af[mt][0], af[mt][1], af[mt][2], af[mt][3],
                        psf + (uint32_t)((mt * 16 * ALDK + kk) * 4));
            #pragma unroll
            for (int nt = 0; nt < 2; nt++) {
                int n = cbase + nt * 8 + gid;
                bf[nt][0] = __float_as_uint(vs[(kk + tig) * ALDV + n]);
                bf[nt][1] = __float_as_uint(vs[(kk + tig + 4) * ALDV + n]);
            }
            #pragma unroll
            for (int mt = 0; mt < 2; mt++)
                #pragma unroll
                for (int nt = 0; nt < 2; nt++)
                    mma_tf32(Oa[mt][nt], af[mt], bf[nt]);
        }

        if (jt + 1 < njt) {
            const int jn = (jt + 1) * 64;
            #pragma unroll
            for (int t = 0; t < 4; t++) {
                int idx = tid + t * 256;
                int r = idx >> 4, c4 = (idx & 15) * 4;
                cp_async16(&qs[r * ALDK + c4], &QVb[(size_t)(jn + r) * EE + c4]);
            }
        }
        CP_COMMIT();
    }

    // ---- reduce l
    #pragma unroll
    for (int mt = 0; mt < 2; mt++) {
        #pragma unroll
        for (int rr = 0; rr < 2; rr++) {
            float v = lacc[mt][rr];
            v += __shfl_xor_sync(0xffffffffu, v, 1);
            v += __shfl_xor_sync(0xffffffffu, v, 2);
            lacc[mt][rr] = v;
        }
    }
    __syncthreads();
    if (tig == 0) {
        #pragma unroll
        for (int mt = 0; mt < 2; mt++) {
            int r = rbase + mt * 16 + gid;
            lsm[r * 4 + wn] = lacc[mt][0];
            lsm[(r + 8) * 4 + wn] = lacc[mt][1];
        }
    }
    __syncthreads();

    float* Ab = g_At + (size_t)b * SS * EE + h * PP;
    #pragma unroll
    for (int mt = 0; mt < 2; mt++) {
        int r = rbase + mt * 16 + gid;
        float inv0 = 1.0f / (lsm[r * 4] + lsm[r * 4 + 1] + lsm[r * 4 + 2] + lsm[r * 4 + 3]);
        int r8 = r + 8;
        float inv1 = 1.0f / (lsm[r8 * 4] + lsm[r8 * 4 + 1] + lsm[r8 * 4 + 2] + lsm[r8 * 4 + 3]);
        #pragma unroll
        for (int nt = 0; nt < 2; nt++) {
            int c = cbase + nt * 8 + 2 * tig;
            *(float2*)&Ab[(size_t)(i0 + r) * EE + c] =
                make_float2(rnd_tf32(Oa[mt][nt][0] * inv0), rnd_tf32(Oa[mt][nt][1] * inv0));
            *(float2*)&Ab[(size_t)(i0 + r8) * EE + c] =
                make_float2(rnd_tf32(Oa[mt][nt][2] * inv1), rnd_tf32(Oa[mt][nt][3] * inv1));
        }
    }
}

// ---------------------------------------------------------------------------
extern "C" void kernel_launch(void* const* d_in, const int* in_sizes, int n_in,
                              void* d_out, int out_size)
{
    const float* x    = (const float*)d_in[0];
    const float* wk   = (const float*)d_in[1];
    const float* wv   = (const float*)d_in[2];
    const float* q    = (const float*)d_in[3];
    const float* lift = (const float*)d_in[4];
    float* out = (float*)d_out;

    static bool attr_done = false;
    if (!attr_done) {
        cudaFuncSetAttribute(proj_tf32_kernel,
            cudaFuncAttributeMaxDynamicSharedMemorySize, GEMM2_SMEM);
        cudaFuncSetAttribute(lift_tf32_kernel,
            cudaFuncAttributeMaxDynamicSharedMemorySize, GEMM2_SMEM);
        cudaFuncSetAttribute(qv_tf32_kernel,
            cudaFuncAttributeMaxDynamicSharedMemorySize, GEMMQ_SMEM);
        cudaFuncSetAttribute(attn_mma_kernel,
            cudaFuncAttributeMaxDynamicSharedMemorySize, ATT_SMEM);
        attr_done = true;
    }

    float *gK, *gV, *gWkT, *gWvT;
    cudaGetSymbolAddress((void**)&gK,  g_K);
    cudaGetSymbolAddress((void**)&gV,  g_V);
    cudaGetSymbolAddress((void**)&gWkT, g_WkT);
    cudaGetSymbolAddress((void**)&gWvT, g_WvT);

    // --- prepass: round + transpose weights only (x/q rounded in-register)
    round_w_kernel<<<(N4_TOTW + 255) / 256, 256>>>(
        (const float4*)wk, (const float4*)wv, (const float4*)lift);

    const int M = BB * SS;

    // --- fused K/V projections (raw x input)
    dim3 gp(EE / BN, M / BM, 2);
    proj_tf32_kernel<<<gp, 256, GEMM2_SMEM>>>(x, gWkT, gWvT, gK, gV);

    // --- QV = Q_h @ Vcat per head (raw q input)
    dim3 gq((BB * PP) / BN, SS / BM, HH);
    qv_tf32_kernel<<<gq, 256, GEMMQ_SMEM>>>(q);

    // --- causal attention (64-row blocks, 3 CTAs/SM)
    dim3 ga(SS / 64, HH, BB);
    attn_mma_kernel<<<ga, 256, ATT_SMEM>>>();

    // --- out = attn @ lifting (fp32 out)
    dim3 gl(EE / BN, M / BM);
    lift_tf32_kernel<<<gl, 256, GEMM2_SMEM>>>(out);
}